// round 16
// baseline (speedup 1.0000x reference)
#include <cuda_runtime.h>
#include <math.h>

#define POOLK 7
#define HH 50
#define WW 50
#define CC 512
#define NROIS 300
#define NPOS (HH * WW)
#define NBF 1250                 // fmax producer blocks (2 positions each)
#define NTASK (NROIS * POOLK)    // 2100 roi consumer blocks

// Device-global scratch (no allocations allowed).
__device__ float g_fmax[NPOS];         // 10 KB channel-max map
__device__ unsigned int g_done;        // fmax blocks completed (reset each launch)
__device__ unsigned int g_fin;         // roi blocks completed (reset each launch)

// ---------------------------------------------------------------------------
// One launch, 3350 SHORT blocks, bid-ordered so wave 1 is pure producers:
//   bid 0..1249   : fmax body (R4-identical) + completion count
//   bid 1250..3349: roi body (R4-identical) + producer-count spin before gather
// Last roi block resets both counters -> deterministic across graph replays.
// ---------------------------------------------------------------------------
__global__ void __launch_bounds__(256) fused_kernel(const float* __restrict__ fm,
                                                    const float* __restrict__ rois,
                                                    float* __restrict__ out) {
    const int tid = threadIdx.x;

    if (blockIdx.x < NBF) {
        // ---------------- fmax producer (R4 fmax body) ----------------------
        const int gid = blockIdx.x * 256 + tid;
        const int pos = gid >> 7;            // 2 positions per block
        const int t = tid & 127;
        const int grp = tid >> 7;
        const int w4 = (tid >> 5) & 3;
        const int lane = tid & 31;

        const float4 v = reinterpret_cast<const float4*>(fm + (size_t)pos * CC)[t];
        float m = fmaxf(fmaxf(v.x, v.y), fmaxf(v.z, v.w));
#pragma unroll
        for (int o = 16; o; o >>= 1)
            m = fmaxf(m, __shfl_xor_sync(0xffffffffu, m, o));

        __shared__ float part[2][4];
        if (lane == 0) part[grp][w4] = m;
        __syncthreads();
        if (t == 0)
            g_fmax[pos] = fmaxf(fmaxf(part[grp][0], part[grp][1]),
                                fmaxf(part[grp][2], part[grp][3]));
        // Publish completion.
        __syncthreads();
        if (tid == 0) {
            __threadfence();                 // make g_fmax stores visible first
            atomicAdd(&g_done, 1u);
        }
        return;
    }

    // ------------------- roi consumer (R4 roi body) -------------------------
    __shared__ float sbin[POOLK];

    const int task = blockIdx.x - NBF;
    const int roi = task / POOLK;
    const int ph = task - roi * POOLK;

    const float* r = rois + roi * 5;
    // truncation matches astype(int32) for nonneg; *0.0625f exact (== /16)
    const int x1 = (int)(r[1] * 0.0625f);
    const int y1 = (int)(r[2] * 0.0625f);
    const int x2 = (int)(r[3] * 0.0625f);
    const int y2 = (int)(r[4] * 0.0625f);
    const int rh = y2 - y1 + 1;
    const int rw = x2 - x1 + 1;

    const int hs = min(max(y1 + (ph * rh) / POOLK, 0), HH);
    const int he = min(max(y1 + ((ph + 1) * rh + POOLK - 1) / POOLK, 0), HH);

    // Wait for all fmax producers (prologue above overlapped with them).
    if (tid == 0) {
        unsigned int v;
        for (;;) {
            asm volatile("ld.acquire.gpu.u32 %0, [%1];"
                         : "=r"(v) : "l"(&g_done) : "memory");
            if (v >= NBF) break;
            __nanosleep(32);
        }
    }
    __syncthreads();                         // broadcast release to all warps

    const int wid = tid >> 5;
    const int lane = tid & 31;

    if (wid < POOLK) {
        const int pw = wid;
        const int ws = min(max(x1 + (pw * rw) / POOLK, 0), WW);
        const int we = min(max(x1 + ((pw + 1) * rw + POOLK - 1) / POOLK, 0), WW);
        const int nh = he - hs;
        const int nw = we - ws;
        const int cnt = (nh > 0 && nw > 0) ? nh * nw : 0;
        float m = -INFINITY;
        for (int e = lane; e < cnt; e += 32) {
            const int dh = e / nw;
            const int dw = e - dh * nw;
            m = fmaxf(m, __ldg(g_fmax + (hs + dh) * WW + (ws + dw)));
        }
#pragma unroll
        for (int o = 16; o; o >>= 1)
            m = fmaxf(m, __shfl_xor_sync(0xffffffffu, m, o));
        if (lane == 0) sbin[pw] = m;
    }
    __syncthreads();

    // Write 7 bins * 512 ch = 896 float4, coalesced; R4-proven paced loop.
    float4* o4 = reinterpret_cast<float4*>(out) + (size_t)task * POOLK * (CC / 4);
    const int n4 = POOLK * (CC / 4);         // 896
    for (int idx = tid; idx < n4; idx += 256) {
        const float v = sbin[idx >> 7];
        o4[idx] = make_float4(v, v, v, v);
    }

    // Completion accounting; the last roi block resets both counters so the
    // next graph replay starts from a clean state (no host-side reset needed).
    __syncthreads();
    if (tid == 0) {
        const unsigned int old = atomicAdd(&g_fin, 1u);
        if (old == NTASK - 1) {
            g_done = 0;
            g_fin = 0;
            __threadfence();
        }
    }
}

extern "C" void kernel_launch(void* const* d_in, const int* in_sizes, int n_in,
                              void* d_out, int out_size) {
    const float* rois = (const float*)d_in[0];
    const float* fm = (const float*)d_in[1];
    if (n_in >= 2 && in_sizes[0] > in_sizes[1]) {
        rois = (const float*)d_in[1];
        fm = (const float*)d_in[0];
    }
    float* out = (float*)d_out;

    fused_kernel<<<NBF + NTASK, 256>>>(fm, rois, out);   // 3350 short blocks
}